// round 11
// baseline (speedup 1.0000x reference)
#include <cuda_runtime.h>
#include <cuda_fp16.h>
#include <cstdint>

// ---------------------------------------------------------------------------
// LSTM layer via fp16 mma.sync GEMM + fused gate epilogue.
//   gates = concat(a, x) @ [Wf;Wi;Wc;Wo]^T + b     (M=16384, N=4096, K=2048)
//   f,i,o = sigmoid; g = tanh; c' = f*c + i*g; a' = o*tanh(c')
// Output: [o | a' | c'] fp32 (each 16384x1024).
//
// R7 experiment: per-k16 MMAs use fp16 ACCUMULATORS with C=0 (single fp16
// rounding per 16-product dot), promoted immediately into fp32 register
// accumulators. If legacy-pipe HMMA f16-acc issues at rt 8 (vs 16 for
// f32-acc), the MMA floor halves; if not, the promote ops hide in the MMA
// shadow and perf is unchanged. Accumulation across K stays fp32 -> error
// adds ~128 independent fp16 roundings (<1e-3 budget).
//
// CTA tile 128(M) x 256(N=64h x 4gates) x 64(K), 8 warps of 64x64, 4-stage
// cp.async pipeline, ldmatrix.x4 fragments, prep kernels convert A (x 1/16)
// and W (x 16, CTA-packed) to fp16 scratch.
// ---------------------------------------------------------------------------

#define M_TILE   128
#define K_TILE   64            // fp16 elements per chunk (128B rows)
#define STAGES   4
#define CHUNKS   32            // K=2048 / 64
#define HD       1024
#define M_TOTAL  16384

#define A_STAGE_BYTES  (128 * 144)
#define B_STAGE_BYTES  (256 * 144)
#define STAGE_BYTES    (A_STAGE_BYTES + B_STAGE_BYTES)   // 55296
#define SMEM_TOTAL     (STAGES * STAGE_BYTES)            // 221184
#define ES             264      // epilogue smem row stride (floats)

#define A_SCALE 0.0625f
#define W_SCALE 16.0f

// fp16 scratch (module-static device memory; allocation-free at launch time)
__device__ __align__(256) __half A16g[(size_t)M_TOTAL * 2048];  // 64 MiB
__device__ __align__(256) __half B16g[(size_t)4096 * 2048];     // 16 MiB

// ---- PTX helpers -----------------------------------------------------------
__device__ __forceinline__ uint32_t smem_u32(const void* p) {
    uint32_t a;
    asm("{ .reg .u64 t; cvta.to.shared.u64 t, %1; cvt.u32.u64 %0, t; }" : "=r"(a) : "l"(p));
    return a;
}

#define CP_ASYNC16(dst_smem, src_gmem) \
    asm volatile("cp.async.cg.shared.global [%0], [%1], 16;" \
        :: "r"((uint32_t)(dst_smem)), "l"(src_gmem) : "memory")
#define CP_COMMIT()  asm volatile("cp.async.commit_group;" ::: "memory")
#define CP_WAIT(n)   asm volatile("cp.async.wait_group %0;" :: "n"(n) : "memory")

#define LDMATRIX_X4(r0, r1, r2, r3, addr) \
    asm volatile("ldmatrix.sync.aligned.m8n8.x4.shared.b16 {%0,%1,%2,%3}, [%4];" \
        : "=r"(r0), "=r"(r1), "=r"(r2), "=r"(r3) : "r"(addr))

// fp16-accumulator MMA, C = 0 (single rounding per k16 dot)
__device__ __forceinline__ void mma_fp16_h(uint32_t& d0, uint32_t& d1,
                                           const uint32_t a[4],
                                           uint32_t b0, uint32_t b1,
                                           uint32_t zero) {
    asm volatile(
        "mma.sync.aligned.m16n8k16.row.col.f16.f16.f16.f16 "
        "{%0,%1}, {%2,%3,%4,%5}, {%6,%7}, {%8,%9};"
        : "=r"(d0), "=r"(d1)
        : "r"(a[0]), "r"(a[1]), "r"(a[2]), "r"(a[3]),
          "r"(b0), "r"(b1), "r"(zero), "r"(zero));
}

__device__ __forceinline__ float tanh_fast(float x) {
    float y; asm("tanh.approx.f32 %0, %1;" : "=f"(y) : "f"(x)); return y;
}
__device__ __forceinline__ float sig_fast(float x) {
    return fmaf(tanh_fast(0.5f * x), 0.5f, 0.5f);
}

// ---------------------------------------------------------------------------
// prep: A16[m][k] = concat(a,x)[m][k] * (1/16), fp16
__global__ __launch_bounds__(256) void prep_A_kernel(
    const float* __restrict__ ga, const float* __restrict__ gx)
{
    const int idx = blockIdx.x * 256 + threadIdx.x;       // 16384*512 threads
    const int m = idx >> 9, pos = idx & 511;
    const int k = pos << 2;
    const float* src = (k < 1024) ? (ga + (size_t)m * 1024 + k)
                                  : (gx + (size_t)m * 1024 + (k - 1024));
    const float4 v = *reinterpret_cast<const float4*>(src);
    __half2 h0 = __floats2half2_rn(v.x * A_SCALE, v.y * A_SCALE);
    __half2 h1 = __floats2half2_rn(v.z * A_SCALE, v.w * A_SCALE);
    uint2 u = make_uint2(*reinterpret_cast<uint32_t*>(&h0),
                         *reinterpret_cast<uint32_t*>(&h1));
    *reinterpret_cast<uint2*>(A16g + (size_t)m * 2048 + k) = u;
}

// prep: B16[row][k], row = hblk*256 + gate*64 + h_local, value = W * 16, fp16
__global__ __launch_bounds__(256) void prep_B_kernel(
    const float* __restrict__ Wf, const float* __restrict__ Wi,
    const float* __restrict__ Wc, const float* __restrict__ Wo)
{
    const int idx = blockIdx.x * 256 + threadIdx.x;       // 4096*512 threads
    const int n2 = idx >> 9, pos = idx & 511;
    const int k = pos << 2;
    const int b = n2 >> 8, g = (n2 >> 6) & 3, hl = n2 & 63;
    const float* Wp = (g == 0) ? Wf : (g == 1) ? Wi : (g == 2) ? Wc : Wo;
    const float4 v = *reinterpret_cast<const float4*>(
        Wp + (size_t)(b * 64 + hl) * 2048 + k);
    __half2 h0 = __floats2half2_rn(v.x * W_SCALE, v.y * W_SCALE);
    __half2 h1 = __floats2half2_rn(v.z * W_SCALE, v.w * W_SCALE);
    uint2 u = make_uint2(*reinterpret_cast<uint32_t*>(&h0),
                         *reinterpret_cast<uint32_t*>(&h1));
    *reinterpret_cast<uint2*>(B16g + (size_t)n2 * 2048 + k) = u;
}

// ---------------------------------------------------------------------------
__global__ __launch_bounds__(256, 1) void lstm_fp16_kernel(
    const float* __restrict__ gc,
    const float* __restrict__ bfp, const float* __restrict__ bip,
    const float* __restrict__ bcp, const float* __restrict__ bop,
    float* __restrict__ out)
{
    extern __shared__ char smem[];
    const uint32_t sb = smem_u32(smem);
    const int tid  = threadIdx.x;
    const int lane = tid & 31;
    const int wid  = tid >> 5;
    const int m0 = blockIdx.y * M_TILE;
    const int h0 = blockIdx.x * 64;

    // 2 (M) x 4 (N) warps of 64x64
    const int wm = (wid >> 2) * 64;
    const int wn = (wid & 3) * 64;

    const int seg = tid & 7;            // 16B segment within 128B k-row
    const int rb  = tid >> 3;           // base row (0..31)

    float acc[4][8][4];
    #pragma unroll
    for (int mt = 0; mt < 4; mt++)
        #pragma unroll
        for (int nt = 0; nt < 8; nt++)
            #pragma unroll
            for (int q = 0; q < 4; q++) acc[mt][nt][q] = 0.0f;

    const __half* Abase = A16g + (size_t)m0 * 2048;
    const __half* Bbase = B16g + (size_t)(blockIdx.x * 256) * 2048;

    auto load_stage = [&](int s, int ch) {
        const uint32_t sAs = sb + s * STAGE_BYTES;
        const uint32_t sBs = sAs + A_STAGE_BYTES;
        const int kh = ch * K_TILE + seg * 8;            // half index in row
        #pragma unroll
        for (int j = 0; j < 4; j++) {                    // A: 128 rows
            const int row = rb + 32 * j;
            CP_ASYNC16(sAs + row * 144 + seg * 16, Abase + (size_t)row * 2048 + kh);
        }
        #pragma unroll
        for (int j = 0; j < 8; j++) {                    // B: 256 rows
            const int n = rb + 32 * j;
            CP_ASYNC16(sBs + n * 144 + seg * 16, Bbase + (size_t)n * 2048 + kh);
        }
        CP_COMMIT();
    };

    #pragma unroll
    for (int s = 0; s < STAGES - 1; s++) load_stage(s, s);

    const int lrow = lane & 15;
    const int lkb  = (lane >> 4) * 16;
    const uint32_t ZERO = 0u;

    #pragma unroll 1
    for (int ch = 0; ch < CHUNKS; ch++) {
        CP_WAIT(STAGES - 2);
        __syncthreads();
        if (ch + STAGES - 1 < CHUNKS) load_stage((ch + STAGES - 1) & (STAGES - 1),
                                                 ch + STAGES - 1);
        else CP_COMMIT();

        const uint32_t sAs = sb + (ch & (STAGES - 1)) * STAGE_BYTES;
        const uint32_t sBs = sAs + A_STAGE_BYTES;

        #pragma unroll
        for (int kk = 0; kk < 4; kk++) {                 // 4 x k16
            const int kb = kk * 32 + lkb;
            uint32_t ra[4][4];
            #pragma unroll
            for (int mt = 0; mt < 4; mt++)
                LDMATRIX_X4(ra[mt][0], ra[mt][1], ra[mt][2], ra[mt][3],
                            sAs + (wm + 16 * mt + lrow) * 144 + kb);
            uint32_t rbf[4][4];
            #pragma unroll
            for (int p = 0; p < 4; p++)
                LDMATRIX_X4(rbf[p][0], rbf[p][1], rbf[p][2], rbf[p][3],
                            sBs + (wn + 16 * p + lrow) * 144 + kb);

            // f16-acc MMA (C=0), immediate fp32 promotion
            #pragma unroll
            for (int mt = 0; mt < 4; mt++)
                #pragma unroll
                for (int nt = 0; nt < 8; nt++) {
                    uint32_t t0, t1;
                    mma_fp16_h(t0, t1, ra[mt],
                               rbf[nt >> 1][nt & 1], rbf[nt >> 1][(nt & 1) + 2],
                               ZERO);
                    const __half2 h0 = *reinterpret_cast<__half2*>(&t0);
                    const __half2 h1 = *reinterpret_cast<__half2*>(&t1);
                    const float2 f0 = __half22float2(h0);
                    const float2 f1 = __half22float2(h1);
                    acc[mt][nt][0] += f0.x;
                    acc[mt][nt][1] += f0.y;
                    acc[mt][nt][2] += f1.x;
                    acc[mt][nt][3] += f1.y;
                }
        }
    }

    // ---- epilogue: stage gates through smem, fuse nonlinearity ----
    CP_WAIT(0);
    __syncthreads();
    float* E = reinterpret_cast<float*>(smem);           // [128][ES]

    #pragma unroll
    for (int mt = 0; mt < 4; mt++) {
        const int r0 = wm + 16 * mt + (lane >> 2);
        #pragma unroll
        for (int nt = 0; nt < 8; nt++) {
            const int cc = wn + 8 * nt + 2 * (lane & 3);
            *reinterpret_cast<float2*>(&E[r0 * ES + cc]) =
                make_float2(acc[mt][nt][0], acc[mt][nt][1]);
            *reinterpret_cast<float2*>(&E[(r0 + 8) * ES + cc]) =
                make_float2(acc[mt][nt][2], acc[mt][nt][3]);
        }
    }
    __syncthreads();

    float* o_out = out;
    float* a_out = out + (size_t)M_TOTAL * HD;
    float* c_out = out + 2 * (size_t)M_TOTAL * HD;

    #pragma unroll 1
    for (int it = 0; it < 8; it++) {
        const int task = tid + 256 * it;                 // 128 m x 16 h-quads
        const int m = task >> 4;
        const int h = (task & 15) * 4;
        const float4 fv = *reinterpret_cast<const float4*>(&E[m * ES + h]);
        const float4 iv = *reinterpret_cast<const float4*>(&E[m * ES + 64 + h]);
        const float4 gv = *reinterpret_cast<const float4*>(&E[m * ES + 128 + h]);
        const float4 ov = *reinterpret_cast<const float4*>(&E[m * ES + 192 + h]);

        const int hg = h0 + h;
        const float4 b_f = *reinterpret_cast<const float4*>(bfp + hg);
        const float4 b_i = *reinterpret_cast<const float4*>(bip + hg);
        const float4 b_c = *reinterpret_cast<const float4*>(bcp + hg);
        const float4 b_o = *reinterpret_cast<const float4*>(bop + hg);

        const size_t base = (size_t)(m0 + m) * HD + hg;
        const float4 cv = *reinterpret_cast<const float4*>(gc + base);

        float fg[4] = {fv.x + b_f.x, fv.y + b_f.y, fv.z + b_f.z, fv.w + b_f.w};
        float ig[4] = {iv.x + b_i.x, iv.y + b_i.y, iv.z + b_i.z, iv.w + b_i.w};
        float gg[4] = {gv.x + b_c.x, gv.y + b_c.y, gv.z + b_c.z, gv.w + b_c.w};
        float og[4] = {ov.x + b_o.x, ov.y + b_o.y, ov.z + b_o.z, ov.w + b_o.w};
        float ci[4] = {cv.x, cv.y, cv.z, cv.w};

        float oo[4], ao[4], co[4];
        #pragma unroll
        for (int q = 0; q < 4; q++) {
            const float f = sig_fast(fg[q]);
            const float i = sig_fast(ig[q]);
            const float g = tanh_fast(gg[q]);
            const float o = sig_fast(og[q]);
            const float cn = fmaf(f, ci[q], i * g);
            oo[q] = o; co[q] = cn; ao[q] = o * tanh_fast(cn);
        }
        *reinterpret_cast<float4*>(o_out + base) = make_float4(oo[0], oo[1], oo[2], oo[3]);
        *reinterpret_cast<float4*>(a_out + base) = make_float4(ao[0], ao[1], ao[2], ao[3]);
        *reinterpret_cast<float4*>(c_out + base) = make_float4(co[0], co[1], co[2], co[3]);
    }
}

// ---------------------------------------------------------------------------
extern "C" void kernel_launch(void* const* d_in, const int* in_sizes, int n_in,
                              void* d_out, int out_size) {
    (void)in_sizes; (void)n_in; (void)out_size;
    const float* x  = (const float*)d_in[0];
    const float* a  = (const float*)d_in[1];
    const float* c  = (const float*)d_in[2];
    const float* Wf = (const float*)d_in[3];
    const float* bf = (const float*)d_in[4];
    const float* Wi = (const float*)d_in[5];
    const float* bi = (const float*)d_in[6];
    const float* Wc = (const float*)d_in[7];
    const float* bc = (const float*)d_in[8];
    const float* Wo = (const float*)d_in[9];
    const float* bo = (const float*)d_in[10];

    static int attr_set = 0;
    if (!attr_set) {
        cudaFuncSetAttribute(lstm_fp16_kernel,
                             cudaFuncAttributeMaxDynamicSharedMemorySize, SMEM_TOTAL);
        attr_set = 1;
    }

    prep_A_kernel<<<(M_TOTAL * 512) / 256, 256>>>(a, x);
    prep_B_kernel<<<(4096 * 512) / 256, 256>>>(Wf, Wi, Wc, Wo);

    dim3 grid(HD / 64, M_TOTAL / M_TILE);      // (16, 128) = 2048 CTAs
    lstm_fp16_kernel<<<grid, 256, SMEM_TOTAL>>>(
        c, bf, bi, bc, bo, (float*)d_out);
}

// round 12
// speedup vs baseline: 1.5880x; 1.5880x over previous
#include <cuda_runtime.h>
#include <cuda_fp16.h>
#include <cstdint>

// ---------------------------------------------------------------------------
// LSTM layer via fp16 mma.sync GEMM (fp32 accum) + fused gate epilogue.
//   gates = concat(a, x) @ [Wf;Wi;Wc;Wo]^T + b     (M=16384, N=4096, K=2048)
//   f,i,o = sigmoid; g = tanh; c' = f*c + i*g; a' = o*tanh(c')
// Output: [o | a' | c'] fp32 (each 16384x1024).
//
// R12: back to f32-acc HMMA (R6 = 97% of legacy-pipe roofline), now with
// OCCUPANCY 2: CTA tile 128(M) x 128(N = 32h x 4gates) x 64(K), 3-stage
// cp.async pipeline (110.6 KB smem/CTA, 2 CTAs/SM), 8 warps of 64x32
// (64 acc regs -> <=128 regs/thread). Two resident CTAs hide each other's
// prologue/epilogue pipe bubbles and halve wave quantization.
// ---------------------------------------------------------------------------

#define M_TILE   128
#define K_TILE   64            // fp16 elements per chunk (128B rows)
#define STAGES   3
#define CHUNKS   32            // K=2048 / 64
#define HD       1024
#define M_TOTAL  16384

#define A_STAGE_BYTES  (128 * 144)
#define B_STAGE_BYTES  (128 * 144)
#define STAGE_BYTES    (A_STAGE_BYTES + B_STAGE_BYTES)   // 36864
#define SMEM_TOTAL     (STAGES * STAGE_BYTES)            // 110592
#define ES             132      // epilogue smem row stride (floats)

#define A_SCALE 0.0625f
#define W_SCALE 16.0f

// fp16 scratch (module-static device memory; allocation-free at launch time)
__device__ __align__(256) __half A16g[(size_t)M_TOTAL * 2048];  // 64 MiB
__device__ __align__(256) __half B16g[(size_t)4096 * 2048];     // 16 MiB

// ---- PTX helpers -----------------------------------------------------------
__device__ __forceinline__ uint32_t smem_u32(const void* p) {
    uint32_t a;
    asm("{ .reg .u64 t; cvta.to.shared.u64 t, %1; cvt.u32.u64 %0, t; }" : "=r"(a) : "l"(p));
    return a;
}

#define CP_ASYNC16(dst_smem, src_gmem) \
    asm volatile("cp.async.cg.shared.global [%0], [%1], 16;" \
        :: "r"((uint32_t)(dst_smem)), "l"(src_gmem) : "memory")
#define CP_COMMIT()  asm volatile("cp.async.commit_group;" ::: "memory")
#define CP_WAIT(n)   asm volatile("cp.async.wait_group %0;" :: "n"(n) : "memory")

#define LDMATRIX_X4(r0, r1, r2, r3, addr) \
    asm volatile("ldmatrix.sync.aligned.m8n8.x4.shared.b16 {%0,%1,%2,%3}, [%4];" \
        : "=r"(r0), "=r"(r1), "=r"(r2), "=r"(r3) : "r"(addr))

__device__ __forceinline__ void mma_fp16(float d[4], const uint32_t a[4],
                                         uint32_t b0, uint32_t b1) {
    asm volatile(
        "mma.sync.aligned.m16n8k16.row.col.f32.f16.f16.f32 "
        "{%0,%1,%2,%3}, {%4,%5,%6,%7}, {%8,%9}, {%0,%1,%2,%3};"
        : "+f"(d[0]), "+f"(d[1]), "+f"(d[2]), "+f"(d[3])
        : "r"(a[0]), "r"(a[1]), "r"(a[2]), "r"(a[3]), "r"(b0), "r"(b1));
}

__device__ __forceinline__ float tanh_fast(float x) {
    float y; asm("tanh.approx.f32 %0, %1;" : "=f"(y) : "f"(x)); return y;
}
__device__ __forceinline__ float sig_fast(float x) {
    return fmaf(tanh_fast(0.5f * x), 0.5f, 0.5f);
}

// ---------------------------------------------------------------------------
// merged prep:
//   blocks [0, 32768):  A16[m][k] = concat(a,x)[m][k] * (1/16)
//   blocks [32768, ..): B16[row][k] = W * 16, row = hblk*128 + gate*32 + hl
__global__ __launch_bounds__(256) void prep_kernel(
    const float* __restrict__ ga, const float* __restrict__ gx,
    const float* __restrict__ Wf, const float* __restrict__ Wi,
    const float* __restrict__ Wc, const float* __restrict__ Wo)
{
    if (blockIdx.x < 32768) {
        const int idx = blockIdx.x * 256 + threadIdx.x;   // 16384 x 512 f4
        const int m = idx >> 9, pos = idx & 511;
        const int k = pos << 2;
        const float* src = (k < 1024) ? (ga + (size_t)m * 1024 + k)
                                      : (gx + (size_t)m * 1024 + (k - 1024));
        const float4 v = *reinterpret_cast<const float4*>(src);
        __half2 h0 = __floats2half2_rn(v.x * A_SCALE, v.y * A_SCALE);
        __half2 h1 = __floats2half2_rn(v.z * A_SCALE, v.w * A_SCALE);
        uint2 u = make_uint2(*reinterpret_cast<uint32_t*>(&h0),
                             *reinterpret_cast<uint32_t*>(&h1));
        *reinterpret_cast<uint2*>(A16g + (size_t)m * 2048 + k) = u;
    } else {
        const int idx = (blockIdx.x - 32768) * 256 + threadIdx.x;  // 4096 x 512
        const int n2 = idx >> 9, pos = idx & 511;
        const int k = pos << 2;
        const int b = n2 >> 7, g = (n2 >> 5) & 3, hl = n2 & 31;
        const float* Wp = (g == 0) ? Wf : (g == 1) ? Wi : (g == 2) ? Wc : Wo;
        const float4 v = *reinterpret_cast<const float4*>(
            Wp + (size_t)(b * 32 + hl) * 2048 + k);
        __half2 h0 = __floats2half2_rn(v.x * W_SCALE, v.y * W_SCALE);
        __half2 h1 = __floats2half2_rn(v.z * W_SCALE, v.w * W_SCALE);
        uint2 u = make_uint2(*reinterpret_cast<uint32_t*>(&h0),
                             *reinterpret_cast<uint32_t*>(&h1));
        *reinterpret_cast<uint2*>(B16g + (size_t)n2 * 2048 + k) = u;
    }
}

// ---------------------------------------------------------------------------
__global__ __launch_bounds__(256, 2) void lstm_fp16_kernel(
    const float* __restrict__ gc,
    const float* __restrict__ bfp, const float* __restrict__ bip,
    const float* __restrict__ bcp, const float* __restrict__ bop,
    float* __restrict__ out)
{
    extern __shared__ char smem[];
    const uint32_t sb = smem_u32(smem);
    const int tid  = threadIdx.x;
    const int lane = tid & 31;
    const int wid  = tid >> 5;
    const int m0 = blockIdx.y * M_TILE;
    const int h0 = blockIdx.x * 32;            // 32 h-cols per CTA

    // 2 (M) x 4 (N) warps of 64x32
    const int wm = (wid >> 2) * 64;
    const int wn = (wid & 3) * 32;

    const int seg = tid & 7;            // 16B segment within 128B k-row
    const int rb  = tid >> 3;           // base row (0..31)

    float acc[4][4][4];
    #pragma unroll
    for (int mt = 0; mt < 4; mt++)
        #pragma unroll
        for (int nt = 0; nt < 4; nt++)
            #pragma unroll
            for (int q = 0; q < 4; q++) acc[mt][nt][q] = 0.0f;

    const __half* Abase = A16g + (size_t)m0 * 2048;
    const __half* Bbase = B16g + (size_t)(blockIdx.x * 128) * 2048;

    auto load_stage = [&](int s, int ch) {
        const uint32_t sAs = sb + s * STAGE_BYTES;
        const uint32_t sBs = sAs + A_STAGE_BYTES;
        const int kh = ch * K_TILE + seg * 8;            // half index in row
        #pragma unroll
        for (int j = 0; j < 4; j++) {                    // A: 128 rows
            const int row = rb + 32 * j;
            CP_ASYNC16(sAs + row * 144 + seg * 16, Abase + (size_t)row * 2048 + kh);
        }
        #pragma unroll
        for (int j = 0; j < 4; j++) {                    // B: 128 rows
            const int n = rb + 32 * j;
            CP_ASYNC16(sBs + n * 144 + seg * 16, Bbase + (size_t)n * 2048 + kh);
        }
        CP_COMMIT();
    };

    load_stage(0, 0);
    load_stage(1, 1);

    const int lrow = lane & 15;
    const int lkb  = (lane >> 4) * 16;

    int s_load = 2, s_comp = 0;
    #pragma unroll 1
    for (int ch = 0; ch < CHUNKS; ch++) {
        CP_WAIT(1);
        __syncthreads();
        if (ch + 2 < CHUNKS) {
            load_stage(s_load, ch + 2);
            if (++s_load == STAGES) s_load = 0;
        } else CP_COMMIT();

        const uint32_t sAs = sb + s_comp * STAGE_BYTES;
        const uint32_t sBs = sAs + A_STAGE_BYTES;
        if (++s_comp == STAGES) s_comp = 0;

        #pragma unroll
        for (int kk = 0; kk < 4; kk++) {                 // 4 x k16
            const int kb = kk * 32 + lkb;
            uint32_t ra[4][4];
            #pragma unroll
            for (int mt = 0; mt < 4; mt++)
                LDMATRIX_X4(ra[mt][0], ra[mt][1], ra[mt][2], ra[mt][3],
                            sAs + (wm + 16 * mt + lrow) * 144 + kb);
            uint32_t rbf[2][4];
            #pragma unroll
            for (int p = 0; p < 2; p++)
                LDMATRIX_X4(rbf[p][0], rbf[p][1], rbf[p][2], rbf[p][3],
                            sBs + (wn + 16 * p + lrow) * 144 + kb);
            #pragma unroll
            for (int mt = 0; mt < 4; mt++)
                #pragma unroll
                for (int nt = 0; nt < 4; nt++)
                    mma_fp16(acc[mt][nt], ra[mt],
                             rbf[nt >> 1][nt & 1], rbf[nt >> 1][(nt & 1) + 2]);
        }
    }

    // ---- epilogue: stage gates through smem, fuse nonlinearity ----
    CP_WAIT(0);
    __syncthreads();
    float* E = reinterpret_cast<float*>(smem);           // [128][ES]

    #pragma unroll
    for (int mt = 0; mt < 4; mt++) {
        const int r0 = wm + 16 * mt + (lane >> 2);
        #pragma unroll
        for (int nt = 0; nt < 4; nt++) {
            const int cc = wn + 8 * nt + 2 * (lane & 3);
            *reinterpret_cast<float2*>(&E[r0 * ES + cc]) =
                make_float2(acc[mt][nt][0], acc[mt][nt][1]);
            *reinterpret_cast<float2*>(&E[(r0 + 8) * ES + cc]) =
                make_float2(acc[mt][nt][2], acc[mt][nt][3]);
        }
    }
    __syncthreads();

    float* o_out = out;
    float* a_out = out + (size_t)M_TOTAL * HD;
    float* c_out = out + 2 * (size_t)M_TOTAL * HD;

    #pragma unroll 1
    for (int it = 0; it < 4; it++) {
        const int task = tid + 256 * it;                 // 128 m x 8 h-quads
        const int m = task >> 3;
        const int h = (task & 7) * 4;
        const float4 fv = *reinterpret_cast<const float4*>(&E[m * ES + h]);
        const float4 iv = *reinterpret_cast<const float4*>(&E[m * ES + 32 + h]);
        const float4 gv = *reinterpret_cast<const float4*>(&E[m * ES + 64 + h]);
        const float4 ov = *reinterpret_cast<const float4*>(&E[m * ES + 96 + h]);

        const int hg = h0 + h;
        const float4 b_f = *reinterpret_cast<const float4*>(bfp + hg);
        const float4 b_i = *reinterpret_cast<const float4*>(bip + hg);
        const float4 b_c = *reinterpret_cast<const float4*>(bcp + hg);
        const float4 b_o = *reinterpret_cast<const float4*>(bop + hg);

        const size_t base = (size_t)(m0 + m) * HD + hg;
        const float4 cv = *reinterpret_cast<const float4*>(gc + base);

        float fg[4] = {fv.x + b_f.x, fv.y + b_f.y, fv.z + b_f.z, fv.w + b_f.w};
        float ig[4] = {iv.x + b_i.x, iv.y + b_i.y, iv.z + b_i.z, iv.w + b_i.w};
        float gg[4] = {gv.x + b_c.x, gv.y + b_c.y, gv.z + b_c.z, gv.w + b_c.w};
        float og[4] = {ov.x + b_o.x, ov.y + b_o.y, ov.z + b_o.z, ov.w + b_o.w};
        float ci[4] = {cv.x, cv.y, cv.z, cv.w};

        float oo[4], ao[4], co[4];
        #pragma unroll
        for (int q = 0; q < 4; q++) {
            const float f = sig_fast(fg[q]);
            const float i = sig_fast(ig[q]);
            const float g = tanh_fast(gg[q]);
            const float o = sig_fast(og[q]);
            const float cn = fmaf(f, ci[q], i * g);
            oo[q] = o; co[q] = cn; ao[q] = o * tanh_fast(cn);
        }
        *reinterpret_cast<float4*>(o_out + base) = make_float4(oo[0], oo[1], oo[2], oo[3]);
        *reinterpret_cast<float4*>(a_out + base) = make_float4(ao[0], ao[1], ao[2], ao[3]);
        *reinterpret_cast<float4*>(c_out + base) = make_float4(co[0], co[1], co[2], co[3]);
    }
}

// ---------------------------------------------------------------------------
extern "C" void kernel_launch(void* const* d_in, const int* in_sizes, int n_in,
                              void* d_out, int out_size) {
    (void)in_sizes; (void)n_in; (void)out_size;
    const float* x  = (const float*)d_in[0];
    const float* a  = (const float*)d_in[1];
    const float* c  = (const float*)d_in[2];
    const float* Wf = (const float*)d_in[3];
    const float* bf = (const float*)d_in[4];
    const float* Wi = (const float*)d_in[5];
    const float* bi = (const float*)d_in[6];
    const float* Wc = (const float*)d_in[7];
    const float* bc = (const float*)d_in[8];
    const float* Wo = (const float*)d_in[9];
    const float* bo = (const float*)d_in[10];

    static int attr_set = 0;
    if (!attr_set) {
        cudaFuncSetAttribute(lstm_fp16_kernel,
                             cudaFuncAttributeMaxDynamicSharedMemorySize, SMEM_TOTAL);
        attr_set = 1;
    }

    prep_kernel<<<32768 + 8192, 256>>>(a, x, Wf, Wi, Wc, Wo);

    dim3 grid(HD / 32, M_TOTAL / M_TILE);      // (32, 128) = 4096 CTAs
    lstm_fp16_kernel<<<grid, 256, SMEM_TOTAL>>>(
        c, bf, bi, bc, bo, (float*)d_out);
}